// round 5
// baseline (speedup 1.0000x reference)
#include <cuda_runtime.h>
#include <cuda_fp16.h>
#include <math.h>

#define BB 64
#define TT 512
#define NN 256
#define DD 128
#define LOG_2PI_F 1.8378770664093453f

// ---------------- device scratch (static globals; no allocs) ----------------
static __device__ float   E_sc[BB * TT * NN];          // emission logprobs [B*T, N] fp32
static __device__ __half2 AhT_g[(NN / 2) * NN];        // packed A^T: [k][j] = (A[2k][j], A[2k+1][j])
static __device__ __half2 WpT_g[DD * NN];              // [d][n] = (-0.5*iv, mu*iv) as half2
static __device__ float   cvec_g[NN];                  // -0.5 * sum_d (mu^2*iv + log_var + LOG2PI)
static __device__ float   logpi_g[NN];
static __device__ float   logprop_g[BB];

// order-preserving float<->uint map for REDUX-based fp max.
// map:   x>=0 -> u|0x80000000 ; x<0 -> ~u
// unmap: high bit set -> u^0x80000000 ; high bit clear -> ~u   (FIXED: was swapped)
__device__ __forceinline__ float warp_max_f(float x) {
    unsigned u = __float_as_uint(x);
    u = ((int)u >= 0) ? (u ^ 0x80000000u) : ~u;
    u = __reduce_max_sync(0xffffffffu, u);
    return ((int)u < 0) ? __uint_as_float(u ^ 0x80000000u) : __uint_as_float(~u);
}

// ---------------- merged prep kernel ----------------
// blocks 0..127   : softmax rows 2k,2k+1 of transition -> AhT_g (packed half2)
// block  128      : log_softmax of state priors -> logpi_g
// blocks 129..256 : W pack + per-state constant (2 states per block)
__global__ void prep_all(const float* __restrict__ trans, const float* __restrict__ pri,
                         const float* __restrict__ mu, const float* __restrict__ lv) {
    __shared__ float redA[8], redB[8];
    int bid = blockIdx.x, t = threadIdx.x;
    int wid = t >> 5, lane = t & 31;

    if (bid < 128) {
        int k = bid;
        float v0 = trans[(2 * k) * NN + t];
        float v1 = trans[(2 * k + 1) * NN + t];
        float m0 = v0, m1 = v1;
#pragma unroll
        for (int o = 16; o; o >>= 1) {
            m0 = fmaxf(m0, __shfl_xor_sync(0xffffffffu, m0, o));
            m1 = fmaxf(m1, __shfl_xor_sync(0xffffffffu, m1, o));
        }
        if (lane == 0) { redA[wid] = m0; redB[wid] = m1; }
        __syncthreads();
        float mb0 = redA[0], mb1 = redB[0];
#pragma unroll
        for (int w = 1; w < 8; w++) { mb0 = fmaxf(mb0, redA[w]); mb1 = fmaxf(mb1, redB[w]); }
        __syncthreads();
        float e0 = expf(v0 - mb0), e1 = expf(v1 - mb1);
        float s0 = e0, s1 = e1;
#pragma unroll
        for (int o = 16; o; o >>= 1) {
            s0 += __shfl_xor_sync(0xffffffffu, s0, o);
            s1 += __shfl_xor_sync(0xffffffffu, s1, o);
        }
        if (lane == 0) { redA[wid] = s0; redB[wid] = s1; }
        __syncthreads();
        float S0 = 0.f, S1 = 0.f;
#pragma unroll
        for (int w = 0; w < 8; w++) { S0 += redA[w]; S1 += redB[w]; }
        AhT_g[k * NN + t] = __floats2half2_rn(e0 / S0, e1 / S1);
    } else if (bid == 128) {
        float v = pri[t];
        float m = v;
#pragma unroll
        for (int o = 16; o; o >>= 1) m = fmaxf(m, __shfl_xor_sync(0xffffffffu, m, o));
        if (lane == 0) redA[wid] = m;
        __syncthreads();
        float mb = redA[0];
#pragma unroll
        for (int w = 1; w < 8; w++) mb = fmaxf(mb, redA[w]);
        __syncthreads();
        float e = expf(v - mb);
        float s = e;
#pragma unroll
        for (int o = 16; o; o >>= 1) s += __shfl_xor_sync(0xffffffffu, s, o);
        if (lane == 0) redA[wid] = s;
        __syncthreads();
        float S = 0.f;
#pragma unroll
        for (int w = 0; w < 8; w++) S += redA[w];
        logpi_g[t] = (v - mb) - logf(S);
    } else {
        int wb = bid - 129;                 // 0..127
        int n = 2 * wb + (t >> 7);
        int d = t & 127;
        float l = lv[n * DD + d];
        float m = mu[n * DD + d];
        float iv = expf(-l);
        WpT_g[d * NN + n] = __floats2half2_rn(-0.5f * iv, m * iv);
        float c = m * m * iv + l + LOG_2PI_F;
#pragma unroll
        for (int o = 16; o; o >>= 1) c += __shfl_xor_sync(0xffffffffu, c, o);
        if (lane == 0) redA[wid] = c;
        __syncthreads();
        if ((t & 127) == 0) {
            int base = (t >> 7) * 4;
            float s = redA[base] + redA[base + 1] + redA[base + 2] + redA[base + 3];
            cvec_g[n] = -0.5f * s;
        }
    }
}

// ---------------- emission GEMM: E[m,n] = sum_d (x^2*w1 + x*w2) + c[n] ----------------
__global__ void __launch_bounds__(256, 1) emis_kernel(const float* __restrict__ X) {
    __shared__ __align__(16) __half2 xp[32 * DD];      // (x^2, x) pairs, [m][d], 16 KB
    int tid = threadIdx.x;
    int r0 = blockIdx.x * 32;

#pragma unroll
    for (int it = 0; it < 16; it++) {
        int idx = it * 256 + tid;                      // coalesced over d
        int m = idx >> 7, d = idx & 127;
        float x = X[(r0 + m) * DD + d];
        xp[idx] = __floats2half2_rn(x * x, x);
    }

    int n = tid;
    __half2 w[DD];
#pragma unroll
    for (int dd = 0; dd < DD; dd++) w[dd] = WpT_g[dd * NN + n];
    float cn = cvec_g[n];
    __syncthreads();

    for (int m = 0; m < 32; m++) {
        const float4* xr = reinterpret_cast<const float4*>(&xp[m * DD]);
        __half2 a0 = __float2half2_rn(0.f), a1 = a0, a2 = a0, a3 = a0;
#pragma unroll
        for (int q = 0; q < 32; q++) {
            float4 v = xr[q];
            const __half2* xv = reinterpret_cast<const __half2*>(&v);
            a0 = __hfma2(w[4 * q + 0], xv[0], a0);
            a1 = __hfma2(w[4 * q + 1], xv[1], a1);
            a2 = __hfma2(w[4 * q + 2], xv[2], a2);
            a3 = __hfma2(w[4 * q + 3], xv[3], a3);
        }
        // fp32 collapse (proven numerics; runs once per 32 HFMA2 iterations)
        float2 f0 = __half22float2(a0), f1 = __half22float2(a1);
        float2 f2 = __half22float2(a2), f3 = __half22float2(a3);
        float s = ((f0.x + f0.y) + (f1.x + f1.y)) + ((f2.x + f2.y) + (f3.x + f3.y)) + cn;
        E_sc[(r0 + m) * NN + n] = s;
    }
}

// ---------------- forward recursion: 1 CTA per batch element ----------------
__global__ void __launch_bounds__(256, 1) forward_rec() {
    __shared__ __align__(16) __half psm[NN];
    __shared__ __align__(16) float red[8];
    int b = blockIdx.x, j = threadIdx.x;
    int wid = j >> 5, lane = j & 31;

    __half2 a[DD];
#pragma unroll
    for (int k = 0; k < DD; k++) a[k] = AhT_g[k * NN + j];

    const float* __restrict__ Erow = E_sc + b * TT * NN;

    // alpha0
    float alpha = logpi_g[j] + Erow[j];
    float m0 = warp_max_f(alpha);
    if (lane == 0) red[wid] = m0;
    __syncthreads();
    float4 ra = *reinterpret_cast<const float4*>(red);
    float4 rb = *reinterpret_cast<const float4*>(red + 4);
    float mprev = fmaxf(fmaxf(fmaxf(ra.x, ra.y), fmaxf(ra.z, ra.w)),
                        fmaxf(fmaxf(rb.x, rb.y), fmaxf(rb.z, rb.w)));
    float p = __expf(alpha - mprev);
    psm[j] = __float2half(p);
    float e_next = Erow[1 * NN + j];
    __syncthreads();

    for (int t = 1; t < TT; t++) {
        float em = e_next + mprev;                       // off the log critical path
        if (t + 1 < TT) e_next = Erow[(t + 1) * NN + j]; // prefetch next row

        // matvec: S = sum_i p_i * A[i][j]
        __half2 acc[8];
#pragma unroll
        for (int i = 0; i < 8; i++) acc[i] = __float2half2_rn(0.f);
        const float4* p4 = reinterpret_cast<const float4*>(psm);
#pragma unroll
        for (int q = 0; q < 32; q++) {
            float4 v = p4[q];                            // broadcast LDS.128
            const __half2* pv = reinterpret_cast<const __half2*>(&v);
            acc[(4 * q + 0) & 7] = __hfma2(a[4 * q + 0], pv[0], acc[(4 * q + 0) & 7]);
            acc[(4 * q + 1) & 7] = __hfma2(a[4 * q + 1], pv[1], acc[(4 * q + 1) & 7]);
            acc[(4 * q + 2) & 7] = __hfma2(a[4 * q + 2], pv[2], acc[(4 * q + 2) & 7]);
            acc[(4 * q + 3) & 7] = __hfma2(a[4 * q + 3], pv[3], acc[(4 * q + 3) & 7]);
        }
        // hadd2 tree collapse (3 levels) then one h2f
        __half2 s0 = __hadd2(acc[0], acc[1]), s1 = __hadd2(acc[2], acc[3]);
        __half2 s2 = __hadd2(acc[4], acc[5]), s3 = __hadd2(acc[6], acc[7]);
        float2 f = __half22float2(__hadd2(__hadd2(s0, s1), __hadd2(s2, s3)));
        float S = f.x + f.y;

        float na = em + __logf(S);

        // block max: REDUX warp max + float4 cross-warp tree
        float mm = warp_max_f(na);
        if (lane == 0) red[wid] = mm;
        __syncthreads();                                 // also fences matvec reads of psm
        float4 r0 = *reinterpret_cast<const float4*>(red);
        float4 r1 = *reinterpret_cast<const float4*>(red + 4);
        float mnew = fmaxf(fmaxf(fmaxf(r0.x, r0.y), fmaxf(r0.z, r0.w)),
                           fmaxf(fmaxf(r1.x, r1.y), fmaxf(r1.z, r1.w)));

        p = __expf(na - mnew);
        psm[j] = __float2half(p);
        mprev = mnew;
        __syncthreads();                                 // psm ready for next step
    }

    // log_prop[b] = mprev + log(sum_j p_j)
    float s = p;
#pragma unroll
    for (int o = 16; o; o >>= 1) s += __shfl_xor_sync(0xffffffffu, s, o);
    if (lane == 0) red[wid] = s;
    __syncthreads();
    if (j == 0) {
        float tot = 0.f;
#pragma unroll
        for (int w = 0; w < 8; w++) tot += red[w];
        logprop_g[b] = mprev + __logf(tot);
    }
}

// ---------------- final: sum log_props over batch ----------------
__global__ void finalize_kernel(float* __restrict__ out) {
    __shared__ float red[2];
    int t = threadIdx.x;                                 // 64 threads
    float v = logprop_g[t];
#pragma unroll
    for (int o = 16; o; o >>= 1) v += __shfl_xor_sync(0xffffffffu, v, o);
    if ((t & 31) == 0) red[t >> 5] = v;
    __syncthreads();
    if (t == 0) out[0] = red[0] + red[1];
}

// ---------------- launch ----------------
extern "C" void kernel_launch(void* const* d_in, const int* in_sizes, int n_in,
                              void* d_out, int out_size) {
    (void)in_sizes; (void)n_in; (void)out_size;
    const float* X     = (const float*)d_in[0];
    const float* mu    = (const float*)d_in[1];
    const float* lv    = (const float*)d_in[2];
    const float* trans = (const float*)d_in[3];
    const float* pri   = (const float*)d_in[4];
    float* out = (float*)d_out;

    prep_all<<<257, 256>>>(trans, pri, mu, lv);
    emis_kernel<<<(BB * TT) / 32, 256>>>(X);
    forward_rec<<<BB, 256>>>();
    finalize_kernel<<<1, 64>>>(out);
}